// round 7
// baseline (speedup 1.0000x reference)
#include <cuda_runtime.h>
#include <cuda_bf16.h>

// out[m, r, t] = X0[r] + t * fl(dt * dXdt[r]),  m=0 -> S, m=1 -> I
// Closed form matches jax associative_scan cumsum to ~2e-7 (verified R2-R4).
//
// R5: two-kernel split. Setup kernel (1 warp) computes the 26 (step, x0)
// pairs into a __device__ global; fill kernel has no scalar prologue, no
// barrier, single-wave grid (1066 CTAs, 256 thr, 12 float4/thread).

#define NROWS 13

static constexpr int THREADS = 256;
static constexpr int VPT     = 12;                  // float4s per thread
static constexpr int EPB     = THREADS * VPT * 4;   // 12288 elems per CTA

__device__ float2 g_params[2 * NROWS];              // (x0, step) per row

__global__ void sei_setup_kernel(const float* __restrict__ S0,
                                 const float* __restrict__ E0,
                                 const float* __restrict__ I0,
                                 const float* __restrict__ L,
                                 const float* __restrict__ beta_p,
                                 const float* __restrict__ gamma_p,
                                 const float* __restrict__ K_p,
                                 const float* __restrict__ Ki_p,
                                 const float* __restrict__ dt_p)
{
    const int y = threadIdx.x;
    if (y >= 2 * NROWS) return;
    const int m = (y >= NROWS) ? 1 : 0;
    const int r = y - m * NROWS;

    const float b  = *beta_p;
    const float g  = *gamma_p;
    const float K  = *K_p;
    const float Ki = *Ki_p;
    const float h  = *dt_p;

    float acc = 0.0f;
    float step, x0;
    if (m == 0) {
        #pragma unroll
        for (int c = 0; c < NROWS; ++c) acc = fmaf(L[r * NROWS + c], S0[c], acc);
        const float dS = -K * acc - b * E0[r] * S0[r] - g * I0[r] * S0[r];
        step = h * dS;
        x0   = S0[r];
    } else {
        #pragma unroll
        for (int c = 0; c < NROWS; ++c) acc = fmaf(L[r * NROWS + c], I0[c], acc);
        const float dI = -Ki * acc + 0.2f * E0[r] - 0.01f * I0[r];
        step = h * dI;
        x0   = I0[r];
    }
    g_params[y] = make_float2(x0, step);
}

__global__ void __launch_bounds__(THREADS)
sei_fill_kernel(float* __restrict__ out, int nt)
{
    const int y = blockIdx.y;                      // row index: m*13 + r
    const float2 p = g_params[y];                  // uniform LDG.64, L2-hit
    const float x0   = p.x;
    const float step = p.y;

    float* __restrict__ row = out + (long long)y * (long long)nt;
    const int t_base = blockIdx.x * EPB;

    if (t_base + EPB <= nt) {
        // Full tile: 3 batches of 4 front-batched STG.128 each.
        #pragma unroll
        for (int bat = 0; bat < VPT / 4; ++bat) {
            float4 v[4];
            int    off[4];
            #pragma unroll
            for (int j = 0; j < 4; ++j) {
                const int idx = bat * 4 + j;
                const int t0 = t_base + (idx * THREADS + threadIdx.x) * 4;
                off[j] = t0;
                const float tf = (float)t0;
                v[j].x = fmaf(tf,        step, x0);
                v[j].y = fmaf(tf + 1.0f, step, x0);
                v[j].z = fmaf(tf + 2.0f, step, x0);
                v[j].w = fmaf(tf + 3.0f, step, x0);
            }
            #pragma unroll
            for (int j = 0; j < 4; ++j)
                *reinterpret_cast<float4*>(row + off[j]) = v[j];
        }
    } else {
        // Tail tile: per-float4 bounds check, scalar at the very end.
        #pragma unroll
        for (int idx = 0; idx < VPT; ++idx) {
            const int t0 = t_base + (idx * THREADS + threadIdx.x) * 4;
            if (t0 + 3 < nt) {
                const float tf = (float)t0;
                float4 v4;
                v4.x = fmaf(tf,        step, x0);
                v4.y = fmaf(tf + 1.0f, step, x0);
                v4.z = fmaf(tf + 2.0f, step, x0);
                v4.w = fmaf(tf + 3.0f, step, x0);
                *reinterpret_cast<float4*>(row + t0) = v4;
            } else if (t0 < nt) {
                for (int t = t0; t < nt; ++t)
                    row[t] = fmaf((float)t, step, x0);
            }
        }
    }
}

extern "C" void kernel_launch(void* const* d_in, const int* in_sizes, int n_in,
                              void* d_out, int out_size)
{
    const float* S0   = (const float*)d_in[0];
    const float* E0   = (const float*)d_in[1];
    const float* I0   = (const float*)d_in[2];
    const float* L    = (const float*)d_in[3];
    const float* beta = (const float*)d_in[4];
    const float* gam  = (const float*)d_in[5];
    const float* K    = (const float*)d_in[6];
    const float* Ki   = (const float*)d_in[7];
    const float* dt   = (const float*)d_in[8];

    const int nt = out_size / (2 * NROWS);
    float* out = (float*)d_out;

    sei_setup_kernel<<<1, 32>>>(S0, E0, I0, L, beta, gam, K, Ki, dt);

    dim3 grid((nt + EPB - 1) / EPB, 2 * NROWS, 1);
    dim3 block(THREADS, 1, 1);
    sei_fill_kernel<<<grid, block>>>(out, nt);
}

// round 8
// speedup vs baseline: 1.0381x; 1.0381x over previous
#include <cuda_runtime.h>
#include <cuda_bf16.h>

// out[m, r, t] = X0[r] + t * fl(dt * dXdt[r]),  m=0 -> S, m=1 -> I
// Closed form matches jax associative_scan cumsum to ~2e-7 (verified R2-R5).
//
// R7: R5's prologue-free fill kernel (10.5us, at the ~2.6KB/cyc L2 write
// ceiling) + PDL to overlap the tiny setup kernel with the fill kernel's
// launch/ramp, removing the ~2us serial second-node cost seen in R5.

#define NROWS 13

static constexpr int THREADS = 256;
static constexpr int VPT     = 12;                  // float4s per thread
static constexpr int EPB     = THREADS * VPT * 4;   // 12288 elems per CTA

__device__ float2 g_params[2 * NROWS];              // (x0, step) per row

__global__ void sei_setup_kernel(const float* __restrict__ S0,
                                 const float* __restrict__ E0,
                                 const float* __restrict__ I0,
                                 const float* __restrict__ L,
                                 const float* __restrict__ beta_p,
                                 const float* __restrict__ gamma_p,
                                 const float* __restrict__ K_p,
                                 const float* __restrict__ Ki_p,
                                 const float* __restrict__ dt_p)
{
    const int y = threadIdx.x;
    if (y < 2 * NROWS) {
        const int m = (y >= NROWS) ? 1 : 0;
        const int r = y - m * NROWS;

        const float b  = *beta_p;
        const float g  = *gamma_p;
        const float K  = *K_p;
        const float Ki = *Ki_p;
        const float h  = *dt_p;

        float acc = 0.0f;
        float step, x0;
        if (m == 0) {
            #pragma unroll
            for (int c = 0; c < NROWS; ++c) acc = fmaf(L[r * NROWS + c], S0[c], acc);
            const float dS = -K * acc - b * E0[r] * S0[r] - g * I0[r] * S0[r];
            step = h * dS;
            x0   = S0[r];
        } else {
            #pragma unroll
            for (int c = 0; c < NROWS; ++c) acc = fmaf(L[r * NROWS + c], I0[c], acc);
            const float dI = -Ki * acc + 0.2f * E0[r] - 0.01f * I0[r];
            step = h * dI;
            x0   = I0[r];
        }
        g_params[y] = make_float2(x0, step);
    }
    // Make g_params visible device-wide, then release the dependent launch.
    __threadfence();
    cudaTriggerProgrammaticLaunchCompletion();
}

__global__ void __launch_bounds__(THREADS)
sei_fill_kernel(float* __restrict__ out, int nt)
{
    const int y = blockIdx.y;                      // row index: m*13 + r
    float* __restrict__ row = out + (long long)y * (long long)nt;
    const int t_base = blockIdx.x * EPB;

    // Wait for the setup kernel's programmatic trigger (g_params ready).
    cudaGridDependencySynchronize();

    const float2 p = g_params[y];                  // uniform LDG.64
    const float x0   = p.x;
    const float step = p.y;

    if (t_base + EPB <= nt) {
        // Full tile: 3 batches of 4 front-batched STG.128 each.
        #pragma unroll
        for (int bat = 0; bat < VPT / 4; ++bat) {
            float4 v[4];
            int    off[4];
            #pragma unroll
            for (int j = 0; j < 4; ++j) {
                const int idx = bat * 4 + j;
                const int t0 = t_base + (idx * THREADS + threadIdx.x) * 4;
                off[j] = t0;
                const float tf = (float)t0;
                v[j].x = fmaf(tf,        step, x0);
                v[j].y = fmaf(tf + 1.0f, step, x0);
                v[j].z = fmaf(tf + 2.0f, step, x0);
                v[j].w = fmaf(tf + 3.0f, step, x0);
            }
            #pragma unroll
            for (int j = 0; j < 4; ++j)
                *reinterpret_cast<float4*>(row + off[j]) = v[j];
        }
    } else {
        // Tail tile: per-float4 bounds check, scalar at the very end.
        #pragma unroll
        for (int idx = 0; idx < VPT; ++idx) {
            const int t0 = t_base + (idx * THREADS + threadIdx.x) * 4;
            if (t0 + 3 < nt) {
                const float tf = (float)t0;
                float4 v4;
                v4.x = fmaf(tf,        step, x0);
                v4.y = fmaf(tf + 1.0f, step, x0);
                v4.z = fmaf(tf + 2.0f, step, x0);
                v4.w = fmaf(tf + 3.0f, step, x0);
                *reinterpret_cast<float4*>(row + t0) = v4;
            } else if (t0 < nt) {
                for (int t = t0; t < nt; ++t)
                    row[t] = fmaf((float)t, step, x0);
            }
        }
    }
}

extern "C" void kernel_launch(void* const* d_in, const int* in_sizes, int n_in,
                              void* d_out, int out_size)
{
    const float* S0   = (const float*)d_in[0];
    const float* E0   = (const float*)d_in[1];
    const float* I0   = (const float*)d_in[2];
    const float* L    = (const float*)d_in[3];
    const float* beta = (const float*)d_in[4];
    const float* gam  = (const float*)d_in[5];
    const float* K    = (const float*)d_in[6];
    const float* Ki   = (const float*)d_in[7];
    const float* dt   = (const float*)d_in[8];

    const int nt = out_size / (2 * NROWS);
    float* out = (float*)d_out;

    sei_setup_kernel<<<1, 32>>>(S0, E0, I0, L, beta, gam, K, Ki, dt);

    // Dependent launch: overlaps with setup; fill waits at
    // cudaGridDependencySynchronize() until setup's trigger fires.
    cudaLaunchConfig_t cfg = {};
    cfg.gridDim  = dim3((nt + EPB - 1) / EPB, 2 * NROWS, 1);
    cfg.blockDim = dim3(THREADS, 1, 1);
    cfg.dynamicSmemBytes = 0;
    cfg.stream = 0;  // legacy default stream (same as <<<>>> above)

    cudaLaunchAttribute attrs[1];
    attrs[0].id = cudaLaunchAttributeProgrammaticStreamSerialization;
    attrs[0].val.programmaticStreamSerializationAllowed = 1;
    cfg.attrs = attrs;
    cfg.numAttrs = 1;

    cudaLaunchKernelEx(&cfg, sei_fill_kernel, out, nt);
}

// round 10
// speedup vs baseline: 1.1604x; 1.1178x over previous
#include <cuda_runtime.h>
#include <cuda_bf16.h>

// out[m, r, t] = X0[r] + t * fl(dt * dXdt[r]),  m=0 -> S, m=1 -> I
// Closed form matches jax associative_scan cumsum to ~2e-7 (verified R2-R7).
//
// R8: back to ONE kernel node (graph replay charges ~2us per extra node —
// measured R5/R7). Prologue made barrier-free: every thread redundantly
// computes (step, x0) for its row (uniform loads, L1-hit after first CTAs;
// fma pipe is >90% idle so the redundant 13-FMA dot product is free).
// Fill body = R5's (best measured: 10.5us, at the ~2.6KB/cyc L2-write cap).

#define NROWS 13

static constexpr int THREADS = 256;
static constexpr int VPT     = 12;                  // float4s per thread
static constexpr int EPB     = THREADS * VPT * 4;   // 12288 elems per CTA

__global__ void __launch_bounds__(THREADS)
sei_fill_kernel(const float* __restrict__ S0,
                const float* __restrict__ E0,
                const float* __restrict__ I0,
                const float* __restrict__ L,
                const float* __restrict__ beta_p,
                const float* __restrict__ gamma_p,
                const float* __restrict__ K_p,
                const float* __restrict__ Ki_p,
                const float* __restrict__ dt_p,
                float* __restrict__ out,
                int nt)
{
    const int y = blockIdx.y;                      // row index: m*13 + r
    const int m = (y >= NROWS) ? 1 : 0;
    const int r = y - m * NROWS;

    // Barrier-free prologue: all threads compute the same (step, x0).
    // Loads are uniform within the CTA (broadcast); L1-resident after the
    // first CTAs on each SM. The 13-wide dot product uses the idle fma pipe.
    float step, x0;
    {
        const float h = __ldg(dt_p);
        float acc = 0.0f;
        if (m == 0) {
            #pragma unroll
            for (int c = 0; c < NROWS; ++c)
                acc = fmaf(__ldg(L + r * NROWS + c), __ldg(S0 + c), acc);
            const float dS = -__ldg(K_p) * acc
                             - __ldg(beta_p)  * __ldg(E0 + r) * __ldg(S0 + r)
                             - __ldg(gamma_p) * __ldg(I0 + r) * __ldg(S0 + r);
            step = h * dS;
            x0   = __ldg(S0 + r);
        } else {
            #pragma unroll
            for (int c = 0; c < NROWS; ++c)
                acc = fmaf(__ldg(L + r * NROWS + c), __ldg(I0 + c), acc);
            const float dI = -__ldg(Ki_p) * acc
                             + 0.2f  * __ldg(E0 + r)
                             - 0.01f * __ldg(I0 + r);
            step = h * dI;
            x0   = __ldg(I0 + r);
        }
    }

    float* __restrict__ row = out + (long long)y * (long long)nt;
    const int t_base = blockIdx.x * EPB;

    if (t_base + EPB <= nt) {
        // Full tile: 3 batches of 4 front-batched STG.128 each.
        #pragma unroll
        for (int bat = 0; bat < VPT / 4; ++bat) {
            float4 v[4];
            int    off[4];
            #pragma unroll
            for (int j = 0; j < 4; ++j) {
                const int idx = bat * 4 + j;
                const int t0 = t_base + (idx * THREADS + threadIdx.x) * 4;
                off[j] = t0;
                const float tf = (float)t0;
                v[j].x = fmaf(tf,        step, x0);
                v[j].y = fmaf(tf + 1.0f, step, x0);
                v[j].z = fmaf(tf + 2.0f, step, x0);
                v[j].w = fmaf(tf + 3.0f, step, x0);
            }
            #pragma unroll
            for (int j = 0; j < 4; ++j)
                *reinterpret_cast<float4*>(row + off[j]) = v[j];
        }
    } else {
        // Tail tile: per-float4 bounds check, scalar at the very end.
        #pragma unroll
        for (int idx = 0; idx < VPT; ++idx) {
            const int t0 = t_base + (idx * THREADS + threadIdx.x) * 4;
            if (t0 + 3 < nt) {
                const float tf = (float)t0;
                float4 v4;
                v4.x = fmaf(tf,        step, x0);
                v4.y = fmaf(tf + 1.0f, step, x0);
                v4.z = fmaf(tf + 2.0f, step, x0);
                v4.w = fmaf(tf + 3.0f, step, x0);
                *reinterpret_cast<float4*>(row + t0) = v4;
            } else if (t0 < nt) {
                for (int t = t0; t < nt; ++t)
                    row[t] = fmaf((float)t, step, x0);
            }
        }
    }
}

extern "C" void kernel_launch(void* const* d_in, const int* in_sizes, int n_in,
                              void* d_out, int out_size)
{
    const float* S0   = (const float*)d_in[0];
    const float* E0   = (const float*)d_in[1];
    const float* I0   = (const float*)d_in[2];
    const float* L    = (const float*)d_in[3];
    const float* beta = (const float*)d_in[4];
    const float* gam  = (const float*)d_in[5];
    const float* K    = (const float*)d_in[6];
    const float* Ki   = (const float*)d_in[7];
    const float* dt   = (const float*)d_in[8];

    const int nt = out_size / (2 * NROWS);
    float* out = (float*)d_out;

    dim3 grid((nt + EPB - 1) / EPB, 2 * NROWS, 1);
    dim3 block(THREADS, 1, 1);
    sei_fill_kernel<<<grid, block>>>(S0, E0, I0, L, beta, gam, K, Ki, dt, out, nt);
}